// round 4
// baseline (speedup 1.0000x reference)
#include <cuda_runtime.h>
#include <cuda_bf16.h>
#include <cstdint>

// ---------------------------------------------------------------------------
// GCN 2-layer encoder:
//   z1 = relu( D^-1/2 (A+I) D^-1/2 (x @ W1) + b1 )
//   out =      D^-1/2 (A+I) D^-1/2 (z1 @ W2) + b2
// Strategy: per-launch CSR build (no float atomics), norm folded as
//   hs = (x@W)*dinv ; out[d] = dinv[d]*(sum_{src in N(d)} hs[src] + hs[d]) + b
// ---------------------------------------------------------------------------

#define MAXN 100000
#define MAXE 3200000
#define INC  512
#define HID  40
#define OUTC 20

// scratch (static device globals; allocation is forbidden)
__device__ int   g_deg[MAXN];
__device__ int   g_off[MAXN];
__device__ int   g_fill[MAXN];
__device__ int   g_bsum[256];
__device__ int   g_bpre[256];
__device__ int   g_csr[MAXE];
__device__ float g_dinv[MAXN];
__device__ float g_hs1[MAXN * HID];   // (x@W1)*dinv
__device__ float g_z1 [MAXN * HID];   // relu layer-1 output
__device__ float g_hs2[MAXN * OUTC];  // (z1@W2)*dinv

// ---- packed f32x2 helpers (Blackwell FFMA2: 2x fp32 FMA throughput) -------
#define FMA_F32X2(d, a, b, c) \
    asm("fma.rn.f32x2 %0, %1, %2, %3;" : "=l"(d) : "l"(a), "l"(b), "l"(c))
#define MUL_F32X2(d, a, b) \
    asm("mul.rn.f32x2 %0, %1, %2;" : "=l"(d) : "l"(a), "l"(b))
#define PACK_F32X2(d, f) \
    asm("mov.b64 %0, {%1, %1};" : "=l"(d) : "f"(f))

typedef unsigned long long u64;

// ---------------------------------------------------------------------------
__global__ void k_zero(int n) {
    int i = blockIdx.x * blockDim.x + threadIdx.x;
    if (i < n) { g_deg[i] = 0; g_fill[i] = 0; }
}

__global__ void k_hist(const int* __restrict__ dst, int E) {
    int e = blockIdx.x * blockDim.x + threadIdx.x;
    if (e < E) atomicAdd(&g_deg[dst[e]], 1);
}

__global__ void k_dinv(int n) {
    int i = blockIdx.x * blockDim.x + threadIdx.x;
    if (i < n) g_dinv[i] = rsqrtf((float)(g_deg[i] + 1));  // +1 self-loop
}

// in-block exclusive scan of g_deg (chunks of 512) -> g_off, block totals
__global__ void k_scan1(int n) {
    __shared__ int s[512];
    int t = threadIdx.x;
    int i = blockIdx.x * 512 + t;
    int v = (i < n) ? g_deg[i] : 0;
    s[t] = v;
    __syncthreads();
    for (int d = 1; d < 512; d <<= 1) {
        int a = (t >= d) ? s[t - d] : 0;
        __syncthreads();
        s[t] += a;
        __syncthreads();
    }
    if (i < n) g_off[i] = s[t] - v;            // in-block exclusive
    if (t == 511) g_bsum[blockIdx.x] = s[511]; // block total
}

__global__ void k_scan2(int nblk) {
    __shared__ int s[256];
    int t = threadIdx.x;
    int v = (t < nblk) ? g_bsum[t] : 0;
    s[t] = v;
    __syncthreads();
    for (int d = 1; d < 256; d <<= 1) {
        int a = (t >= d) ? s[t - d] : 0;
        __syncthreads();
        s[t] += a;
        __syncthreads();
    }
    if (t < nblk) g_bpre[t] = s[t] - v;        // exclusive prefix of totals
}

__global__ void k_scan3(int n) {
    int i = blockIdx.x * blockDim.x + threadIdx.x;
    if (i < n) g_off[i] += g_bpre[i >> 9];
}

__global__ void k_fill(const int* __restrict__ src, const int* __restrict__ dst, int E) {
    int e = blockIdx.x * blockDim.x + threadIdx.x;
    if (e < E) {
        int d = dst[e];
        int p = atomicAdd(&g_fill[d], 1);
        g_csr[g_off[d] + p] = src[e];
    }
}

// ---------------------------------------------------------------------------
// GEMM1: hs1[i][c] = dinv[i] * sum_k x[i][k] * W1[k][c]   (c = 0..39)
// 128 nodes/block, 128 threads, K tiled by 32, f32x2 accumulation.
// ---------------------------------------------------------------------------
__global__ void __launch_bounds__(128) k_gemm1(const float* __restrict__ x,
                                               const float* __restrict__ W1,
                                               int n) {
    __shared__ float xt[128 * 33];
    __shared__ __align__(16) float Ws[32 * HID];
    int t = threadIdx.x;
    int node = blockIdx.x * 128 + t;
    u64 acc[HID / 2];
#pragma unroll
    for (int j = 0; j < HID / 2; j++) acc[j] = 0ULL;

    for (int k0 = 0; k0 < INC; k0 += 32) {
        __syncthreads();
        // W chunk: 32x40 floats, rows contiguous in W1
#pragma unroll
        for (int i = 0; i < 10; i++)
            Ws[t + i * 128] = W1[k0 * HID + t + i * 128];
        // x tile: 128 nodes x 32 k, coalesced flat load
#pragma unroll
        for (int i = 0; i < 32; i++) {
            int e = t + i * 128;
            int nn = e >> 5, kk = e & 31;
            int gnode = blockIdx.x * 128 + nn;
            float v = (gnode < n) ? x[(size_t)gnode * INC + k0 + kk] : 0.0f;
            xt[nn * 33 + kk] = v;
        }
        __syncthreads();
        const ulonglong2* Wv = (const ulonglong2*)Ws;
#pragma unroll
        for (int k = 0; k < 32; k++) {
            float xv = xt[t * 33 + k];
            u64 xx; PACK_F32X2(xx, xv);
#pragma unroll
            for (int jj = 0; jj < 10; jj++) {
                ulonglong2 w = Wv[k * 10 + jj];
                FMA_F32X2(acc[2 * jj],     xx, w.x, acc[2 * jj]);
                FMA_F32X2(acc[2 * jj + 1], xx, w.y, acc[2 * jj + 1]);
            }
        }
    }
    if (node < n) {
        float di = g_dinv[node];
        u64 dd; PACK_F32X2(dd, di);
        u64* outp = (u64*)&g_hs1[(size_t)node * HID];
#pragma unroll
        for (int j = 0; j < HID / 2; j++) {
            u64 r; MUL_F32X2(r, acc[j], dd);
            outp[j] = r;
        }
    }
}

// ---------------------------------------------------------------------------
// Aggregation layer 1: 10 threads/node, float4 each (40 ch), gather from CSR.
// z1 = relu(dinv * (self + sum) + b1)
// ---------------------------------------------------------------------------
__global__ void __launch_bounds__(320) k_agg1(const float* __restrict__ b1, int n) {
    int t = threadIdx.x;
    int node = blockIdx.x * 32 + t / 10;
    int c4 = (t % 10) * 4;
    if (node >= n) return;
    const float* __restrict__ hs = g_hs1;
    float4 acc = *(const float4*)&hs[(size_t)node * HID + c4];  // self term
    int o = g_off[node];
    int dcnt = g_deg[node];
    int j = 0;
    for (; j + 2 <= dcnt; j += 2) {
        int s0 = __ldg(&g_csr[o + j]);
        int s1 = __ldg(&g_csr[o + j + 1]);
        float4 v0 = *(const float4*)&hs[(size_t)s0 * HID + c4];
        float4 v1 = *(const float4*)&hs[(size_t)s1 * HID + c4];
        acc.x += v0.x; acc.y += v0.y; acc.z += v0.z; acc.w += v0.w;
        acc.x += v1.x; acc.y += v1.y; acc.z += v1.z; acc.w += v1.w;
    }
    if (j < dcnt) {
        int s0 = __ldg(&g_csr[o + j]);
        float4 v0 = *(const float4*)&hs[(size_t)s0 * HID + c4];
        acc.x += v0.x; acc.y += v0.y; acc.z += v0.z; acc.w += v0.w;
    }
    float di = g_dinv[node];
    float4 r;
    r.x = fmaxf(di * acc.x + __ldg(&b1[c4 + 0]), 0.0f);
    r.y = fmaxf(di * acc.y + __ldg(&b1[c4 + 1]), 0.0f);
    r.z = fmaxf(di * acc.z + __ldg(&b1[c4 + 2]), 0.0f);
    r.w = fmaxf(di * acc.w + __ldg(&b1[c4 + 3]), 0.0f);
    *(float4*)&g_z1[(size_t)node * HID + c4] = r;
}

// ---------------------------------------------------------------------------
// GEMM2: hs2[i][c] = dinv[i] * sum_k z1[i][k] * W2[k][c]  (K=40, C=20)
// ---------------------------------------------------------------------------
__global__ void __launch_bounds__(128) k_gemm2(const float* __restrict__ W2, int n) {
    __shared__ float zt[128 * 41];
    __shared__ __align__(16) float W2s[HID * OUTC];
    int t = threadIdx.x;
    int node = blockIdx.x * 128 + t;
    for (int i = t; i < HID * OUTC; i += 128) W2s[i] = W2[i];
#pragma unroll
    for (int i = 0; i < HID; i++) {
        int e = t + i * 128;
        int nn = e / HID, kk = e % HID;
        int gnode = blockIdx.x * 128 + nn;
        zt[nn * 41 + kk] = (gnode < n) ? g_z1[(size_t)gnode * HID + kk] : 0.0f;
    }
    __syncthreads();
    float acc[OUTC];
#pragma unroll
    for (int c = 0; c < OUTC; c++) acc[c] = 0.0f;
#pragma unroll
    for (int k = 0; k < HID; k++) {
        float zv = zt[t * 41 + k];
#pragma unroll
        for (int c4 = 0; c4 < 5; c4++) {
            float4 w = *(const float4*)&W2s[k * OUTC + c4 * 4];
            acc[c4 * 4 + 0] = fmaf(zv, w.x, acc[c4 * 4 + 0]);
            acc[c4 * 4 + 1] = fmaf(zv, w.y, acc[c4 * 4 + 1]);
            acc[c4 * 4 + 2] = fmaf(zv, w.z, acc[c4 * 4 + 2]);
            acc[c4 * 4 + 3] = fmaf(zv, w.w, acc[c4 * 4 + 3]);
        }
    }
    if (node < n) {
        float di = g_dinv[node];
#pragma unroll
        for (int c = 0; c < OUTC; c++)
            g_hs2[(size_t)node * OUTC + c] = di * acc[c];
    }
}

// ---------------------------------------------------------------------------
// Aggregation layer 2: 5 threads/node, float4 each (20 ch). Writes d_out.
// ---------------------------------------------------------------------------
__global__ void __launch_bounds__(320) k_agg2(const float* __restrict__ b2,
                                              float* __restrict__ out, int n) {
    int t = threadIdx.x;
    int node = blockIdx.x * 64 + t / 5;
    int c4 = (t % 5) * 4;
    if (node >= n) return;
    const float* __restrict__ hs = g_hs2;
    float4 acc = *(const float4*)&hs[(size_t)node * OUTC + c4];  // self term
    int o = g_off[node];
    int dcnt = g_deg[node];
    int j = 0;
    for (; j + 2 <= dcnt; j += 2) {
        int s0 = __ldg(&g_csr[o + j]);
        int s1 = __ldg(&g_csr[o + j + 1]);
        float4 v0 = *(const float4*)&hs[(size_t)s0 * OUTC + c4];
        float4 v1 = *(const float4*)&hs[(size_t)s1 * OUTC + c4];
        acc.x += v0.x; acc.y += v0.y; acc.z += v0.z; acc.w += v0.w;
        acc.x += v1.x; acc.y += v1.y; acc.z += v1.z; acc.w += v1.w;
    }
    if (j < dcnt) {
        int s0 = __ldg(&g_csr[o + j]);
        float4 v0 = *(const float4*)&hs[(size_t)s0 * OUTC + c4];
        acc.x += v0.x; acc.y += v0.y; acc.z += v0.z; acc.w += v0.w;
    }
    float di = g_dinv[node];
    float4 r;
    r.x = di * acc.x + __ldg(&b2[c4 + 0]);
    r.y = di * acc.y + __ldg(&b2[c4 + 1]);
    r.z = di * acc.z + __ldg(&b2[c4 + 2]);
    r.w = di * acc.w + __ldg(&b2[c4 + 3]);
    *(float4*)&out[(size_t)node * OUTC + c4] = r;
}

// ---------------------------------------------------------------------------
extern "C" void kernel_launch(void* const* d_in, const int* in_sizes, int n_in,
                              void* d_out, int out_size) {
    const float* x  = (const float*)d_in[0];
    const int*   ei = (const int*)  d_in[1];
    const float* W1 = (const float*)d_in[2];
    const float* b1 = (const float*)d_in[3];
    const float* W2 = (const float*)d_in[4];
    const float* b2 = (const float*)d_in[5];
    float* out = (float*)d_out;

    int n = in_sizes[0] / INC;   // 100000
    int E = in_sizes[1] / 2;     // 3200000
    const int* src = ei;
    const int* dst = ei + E;

    int nb_n  = (n + 255) / 256;
    int nb_e  = (E + 255) / 256;
    int nblk  = (n + 511) / 512;        // scan chunks (<=256)

    // CSR build + norms
    k_zero <<<nb_n, 256>>>(n);
    k_hist <<<nb_e, 256>>>(dst, E);
    k_dinv <<<nb_n, 256>>>(n);
    k_scan1<<<nblk, 512>>>(n);
    k_scan2<<<1, 256>>>(nblk);
    k_scan3<<<nb_n, 256>>>(n);
    k_fill <<<nb_e, 256>>>(src, dst, E);

    // layer 1
    k_gemm1<<<(n + 127) / 128, 128>>>(x, W1, n);
    k_agg1 <<<(n + 31) / 32, 320>>>(b1, n);

    // layer 2
    k_gemm2<<<(n + 127) / 128, 128>>>(W2, n);
    k_agg2 <<<(n + 63) / 64, 320>>>(b2, out, n);
}

// round 8
// speedup vs baseline: 1.7204x; 1.7204x over previous
#include <cuda_runtime.h>
#include <cuda_bf16.h>
#include <cstdint>

// ---------------------------------------------------------------------------
// GCN 2-layer encoder:
//   z1 = relu( D^-1/2 (A+I) D^-1/2 (x @ W1) + b1 )
//   out =      D^-1/2 (A+I) D^-1/2 (z1 @ W2) + b2
// Norm folded: hs = (x@W)*dinv ; out[d] = dinv[d]*(sum_{s in N(d)} hs[s] + hs[d]) + b
// Per-launch CSR build (hist + scan + atomic fill), gather-only aggregation.
// gemm1: 2 nodes/thread (halved smem traffic, FMA-bound), f32x2 FFMA2 path.
// gemm2 fused into agg1 via smem z1 exchange. 4-way unrolled float4 gathers.
// ---------------------------------------------------------------------------

#define MAXN 100000
#define MAXE 3200000
#define INC  512
#define HID  40
#define OUTC 20

__device__ int   g_deg[MAXN];
__device__ int   g_off[MAXN];
__device__ int   g_fill[MAXN];
__device__ int   g_bsum[256];
__device__ int   g_bpre[256];
__device__ int   g_csr[MAXE];
__device__ float g_dinv[MAXN];
__device__ float g_hs1[MAXN * HID];   // (x@W1)*dinv
__device__ float g_hs2[MAXN * OUTC];  // (z1@W2)*dinv

// ---- packed f32x2 helpers (Blackwell FFMA2: 2x fp32 FMA throughput) -------
#define FMA_F32X2(d, a, b, c) \
    asm("fma.rn.f32x2 %0, %1, %2, %3;" : "=l"(d) : "l"(a), "l"(b), "l"(c))
#define MUL_F32X2(d, a, b) \
    asm("mul.rn.f32x2 %0, %1, %2;" : "=l"(d) : "l"(a), "l"(b))
#define PACK_F32X2(d, f) \
    asm("mov.b64 %0, {%1, %1};" : "=l"(d) : "f"(f))

typedef unsigned long long u64;

// ---------------------------------------------------------------------------
__global__ void k_zero(int n) {
    int i = blockIdx.x * blockDim.x + threadIdx.x;
    if (i < n) { g_deg[i] = 0; g_fill[i] = 0; }
}

__global__ void k_hist(const int* __restrict__ dst, int E) {
    int e = blockIdx.x * blockDim.x + threadIdx.x;
    if (e < E) atomicAdd(&g_deg[dst[e]], 1);
}

__global__ void k_dinv(int n) {
    int i = blockIdx.x * blockDim.x + threadIdx.x;
    if (i < n) g_dinv[i] = rsqrtf((float)(g_deg[i] + 1));  // +1 self-loop
}

// in-block exclusive scan of g_deg (chunks of 512) -> g_off, block totals
__global__ void k_scan1(int n) {
    __shared__ int s[512];
    int t = threadIdx.x;
    int i = blockIdx.x * 512 + t;
    int v = (i < n) ? g_deg[i] : 0;
    s[t] = v;
    __syncthreads();
    for (int d = 1; d < 512; d <<= 1) {
        int a = (t >= d) ? s[t - d] : 0;
        __syncthreads();
        s[t] += a;
        __syncthreads();
    }
    if (i < n) g_off[i] = s[t] - v;
    if (t == 511) g_bsum[blockIdx.x] = s[511];
}

__global__ void k_scan2(int nblk) {
    __shared__ int s[256];
    int t = threadIdx.x;
    int v = (t < nblk) ? g_bsum[t] : 0;
    s[t] = v;
    __syncthreads();
    for (int d = 1; d < 256; d <<= 1) {
        int a = (t >= d) ? s[t - d] : 0;
        __syncthreads();
        s[t] += a;
        __syncthreads();
    }
    if (t < nblk) g_bpre[t] = s[t] - v;
}

__global__ void k_scan3(int n) {
    int i = blockIdx.x * blockDim.x + threadIdx.x;
    if (i < n) g_off[i] += g_bpre[i >> 9];
}

__global__ void k_fill(const int* __restrict__ src, const int* __restrict__ dst, int E) {
    int e = blockIdx.x * blockDim.x + threadIdx.x;
    if (e < E) {
        int d = dst[e];
        int p = atomicAdd(&g_fill[d], 1);
        g_csr[g_off[d] + p] = src[e];
    }
}

// ---------------------------------------------------------------------------
// GEMM1: hs1[i][c] = dinv[i] * sum_k x[i][k] * W1[k][c]
// 256 nodes/block, 128 threads, 2 nodes/thread (rows t and t+128),
// K tiled by 32, f32x2 accumulation. W smem traffic amortized over 2x FMAs.
// ---------------------------------------------------------------------------
__global__ void __launch_bounds__(128) k_gemm1(const float* __restrict__ x,
                                               const float* __restrict__ W1,
                                               int n) {
    __shared__ float xt[256 * 33];                 // 33.8 KB, pad 33 -> conflict-free
    __shared__ __align__(16) float Ws[32 * HID];   // 5.1 KB
    int t = threadIdx.x;
    int nbase = blockIdx.x * 256;
    u64 accA[HID / 2], accB[HID / 2];
#pragma unroll
    for (int j = 0; j < HID / 2; j++) { accA[j] = 0ULL; accB[j] = 0ULL; }

    for (int k0 = 0; k0 < INC; k0 += 32) {
        __syncthreads();
        // W chunk: 32 rows x 40 cols, contiguous in W1
#pragma unroll
        for (int i = 0; i < 10; i++)
            Ws[t + i * 128] = W1[k0 * HID + t + i * 128];
        // x tile: 256 nodes x 32 k, float4 loads (2048 float4, 16/thread)
#pragma unroll
        for (int i = 0; i < 16; i++) {
            int idx = t + i * 128;
            int nn = idx >> 3;
            int kk = (idx & 7) << 2;
            int gnode = nbase + nn;
            float4 v = make_float4(0.f, 0.f, 0.f, 0.f);
            if (gnode < n) v = *(const float4*)&x[(size_t)gnode * INC + k0 + kk];
            xt[nn * 33 + kk + 0] = v.x;
            xt[nn * 33 + kk + 1] = v.y;
            xt[nn * 33 + kk + 2] = v.z;
            xt[nn * 33 + kk + 3] = v.w;
        }
        __syncthreads();
        const ulonglong2* Wv = (const ulonglong2*)Ws;
#pragma unroll 8
        for (int k = 0; k < 32; k++) {
            float a0 = xt[t * 33 + k];
            float a1 = xt[(t + 128) * 33 + k];
            u64 x0, x1;
            PACK_F32X2(x0, a0);
            PACK_F32X2(x1, a1);
#pragma unroll
            for (int jj = 0; jj < 10; jj++) {
                ulonglong2 w = Wv[k * 10 + jj];
                FMA_F32X2(accA[2 * jj],     x0, w.x, accA[2 * jj]);
                FMA_F32X2(accA[2 * jj + 1], x0, w.y, accA[2 * jj + 1]);
                FMA_F32X2(accB[2 * jj],     x1, w.x, accB[2 * jj]);
                FMA_F32X2(accB[2 * jj + 1], x1, w.y, accB[2 * jj + 1]);
            }
        }
    }
    int na = nbase + t;
    int nb = nbase + 128 + t;
    if (na < n) {
        float di = g_dinv[na];
        u64 dd; PACK_F32X2(dd, di);
        u64* op = (u64*)&g_hs1[(size_t)na * HID];
#pragma unroll
        for (int j = 0; j < HID / 2; j++) { u64 r; MUL_F32X2(r, accA[j], dd); op[j] = r; }
    }
    if (nb < n) {
        float di = g_dinv[nb];
        u64 dd; PACK_F32X2(dd, di);
        u64* op = (u64*)&g_hs1[(size_t)nb * HID];
#pragma unroll
        for (int j = 0; j < HID / 2; j++) { u64 r; MUL_F32X2(r, accB[j], dd); op[j] = r; }
    }
}

// ---------------------------------------------------------------------------
// Fused aggregation-1 + GEMM2:
//   z1 row computed in-block (10 threads/node, float4 gathers, 4-way unroll),
//   exchanged via smem, then each thread computes 2 output channels of
//   hs2 = dinv * (z1 @ W2). Eliminates z1 global round-trip.
// ---------------------------------------------------------------------------
__global__ void __launch_bounds__(320) k_agg1g2(const float* __restrict__ b1,
                                                const float* __restrict__ W2,
                                                int n) {
    __shared__ float z1s[32 * HID];          // 5.1 KB
    __shared__ float W2s[HID * OUTC];        // 3.2 KB
    int t = threadIdx.x;
    for (int i = t; i < HID * OUTC; i += 320) W2s[i] = W2[i];

    int ln = t / 10;                 // local node 0..31
    int lane10 = t % 10;
    int node = blockIdx.x * 32 + ln;
    int c4 = lane10 * 4;
    bool valid = (node < n);
    float di = 0.0f;

    if (valid) {
        const float* __restrict__ hs = g_hs1;
        float4 acc = __ldg((const float4*)&hs[(size_t)node * HID + c4]);  // self
        int o = g_off[node];
        int dcnt = g_deg[node];
        di = g_dinv[node];
        int j = 0;
        for (; j + 4 <= dcnt; j += 4) {
            int s0 = __ldg(&g_csr[o + j]);
            int s1 = __ldg(&g_csr[o + j + 1]);
            int s2 = __ldg(&g_csr[o + j + 2]);
            int s3 = __ldg(&g_csr[o + j + 3]);
            float4 v0 = __ldg((const float4*)&hs[(size_t)s0 * HID + c4]);
            float4 v1 = __ldg((const float4*)&hs[(size_t)s1 * HID + c4]);
            float4 v2 = __ldg((const float4*)&hs[(size_t)s2 * HID + c4]);
            float4 v3 = __ldg((const float4*)&hs[(size_t)s3 * HID + c4]);
            acc.x += v0.x + v1.x + v2.x + v3.x;
            acc.y += v0.y + v1.y + v2.y + v3.y;
            acc.z += v0.z + v1.z + v2.z + v3.z;
            acc.w += v0.w + v1.w + v2.w + v3.w;
        }
        for (; j < dcnt; j++) {
            int s0 = __ldg(&g_csr[o + j]);
            float4 v0 = __ldg((const float4*)&hs[(size_t)s0 * HID + c4]);
            acc.x += v0.x; acc.y += v0.y; acc.z += v0.z; acc.w += v0.w;
        }
        z1s[ln * HID + c4 + 0] = fmaxf(di * acc.x + __ldg(&b1[c4 + 0]), 0.0f);
        z1s[ln * HID + c4 + 1] = fmaxf(di * acc.y + __ldg(&b1[c4 + 1]), 0.0f);
        z1s[ln * HID + c4 + 2] = fmaxf(di * acc.z + __ldg(&b1[c4 + 2]), 0.0f);
        z1s[ln * HID + c4 + 3] = fmaxf(di * acc.w + __ldg(&b1[c4 + 3]), 0.0f);
    }
    __syncthreads();

    // GEMM2: 2 channels per thread (10 threads x 2 = 20 channels)
    if (valid) {
        int c = lane10 * 2;
        float s0 = 0.0f, s1 = 0.0f;
#pragma unroll
        for (int k = 0; k < HID; k++) {
            float z = z1s[ln * HID + k];
            s0 = fmaf(z, W2s[k * OUTC + c],     s0);
            s1 = fmaf(z, W2s[k * OUTC + c + 1], s1);
        }
        g_hs2[(size_t)node * OUTC + c]     = di * s0;
        g_hs2[(size_t)node * OUTC + c + 1] = di * s1;
    }
}

// ---------------------------------------------------------------------------
// Aggregation layer 2: 5 threads/node, float4 each (20 ch), 4-way unroll.
// out[d] = dinv[d]*(sum hs2[s] + hs2[d]) + b2
// ---------------------------------------------------------------------------
__global__ void __launch_bounds__(320) k_agg2(const float* __restrict__ b2,
                                              float* __restrict__ out, int n) {
    int t = threadIdx.x;
    int node = blockIdx.x * 64 + t / 5;
    int c4 = (t % 5) * 4;
    if (node >= n) return;
    const float* __restrict__ hs = g_hs2;
    float4 acc = __ldg((const float4*)&hs[(size_t)node * OUTC + c4]);  // self
    int o = g_off[node];
    int dcnt = g_deg[node];
    int j = 0;
    for (; j + 4 <= dcnt; j += 4) {
        int s0 = __ldg(&g_csr[o + j]);
        int s1 = __ldg(&g_csr[o + j + 1]);
        int s2 = __ldg(&g_csr[o + j + 2]);
        int s3 = __ldg(&g_csr[o + j + 3]);
        float4 v0 = __ldg((const float4*)&hs[(size_t)s0 * OUTC + c4]);
        float4 v1 = __ldg((const float4*)&hs[(size_t)s1 * OUTC + c4]);
        float4 v2 = __ldg((const float4*)&hs[(size_t)s2 * OUTC + c4]);
        float4 v3 = __ldg((const float4*)&hs[(size_t)s3 * OUTC + c4]);
        acc.x += v0.x + v1.x + v2.x + v3.x;
        acc.y += v0.y + v1.y + v2.y + v3.y;
        acc.z += v0.z + v1.z + v2.z + v3.z;
        acc.w += v0.w + v1.w + v2.w + v3.w;
    }
    for (; j < dcnt; j++) {
        int s0 = __ldg(&g_csr[o + j]);
        float4 v0 = __ldg((const float4*)&hs[(size_t)s0 * OUTC + c4]);
        acc.x += v0.x; acc.y += v0.y; acc.z += v0.z; acc.w += v0.w;
    }
    float di = g_dinv[node];
    float4 r;
    r.x = di * acc.x + __ldg(&b2[c4 + 0]);
    r.y = di * acc.y + __ldg(&b2[c4 + 1]);
    r.z = di * acc.z + __ldg(&b2[c4 + 2]);
    r.w = di * acc.w + __ldg(&b2[c4 + 3]);
    *(float4*)&out[(size_t)node * OUTC + c4] = r;
}

// ---------------------------------------------------------------------------
extern "C" void kernel_launch(void* const* d_in, const int* in_sizes, int n_in,
                              void* d_out, int out_size) {
    const float* x  = (const float*)d_in[0];
    const int*   ei = (const int*)  d_in[1];
    const float* W1 = (const float*)d_in[2];
    const float* b1 = (const float*)d_in[3];
    const float* W2 = (const float*)d_in[4];
    const float* b2 = (const float*)d_in[5];
    float* out = (float*)d_out;

    int n = in_sizes[0] / INC;   // 100000
    int E = in_sizes[1] / 2;     // 3200000
    const int* src = ei;
    const int* dst = ei + E;

    int nb_n = (n + 255) / 256;
    int nb_e = (E + 255) / 256;
    int nblk = (n + 511) / 512;

    // launch idx:                       dependencies
    k_zero  <<<nb_n, 256>>>(n);              // 0
    k_hist  <<<nb_e, 256>>>(dst, E);         // 1
    k_dinv  <<<nb_n, 256>>>(n);              // 2  (deg)
    k_gemm1 <<<(n + 255) / 256, 128>>>(x, W1, n);  // 3  (dinv only) — ncu window
    k_scan1 <<<nblk, 512>>>(n);              // 4
    k_scan2 <<<1, 256>>>(nblk);              // 5
    k_scan3 <<<nb_n, 256>>>(n);              // 6
    k_fill  <<<nb_e, 256>>>(src, dst, E);    // 7
    k_agg1g2<<<(n + 31) / 32, 320>>>(b1, W2, n);   // 8  (hs1 + CSR) -> hs2
    k_agg2  <<<(n + 63) / 64, 320>>>(b2, out, n);  // 9
}

// round 10
// speedup vs baseline: 1.7906x; 1.0409x over previous
#include <cuda_runtime.h>
#include <cuda_bf16.h>
#include <cstdint>

// ---------------------------------------------------------------------------
// GCN 2-layer encoder:
//   z1 = relu( D^-1/2 (A+I) D^-1/2 (x @ W1) + b1 )
//   out =      D^-1/2 (A+I) D^-1/2 (z1 @ W2) + b2
// Norm folded: hs = (x@W)*dinv ; out[d] = dinv[d]*(sum_{s in N(d)} hs[s] + hs[d]) + b
// Per-launch CSR build, gather-only aggregation, gemm2 fused into agg1.
// Round 8: gemm1 software-prefetched inner loop (W row k+1 + x k+1 in regs),
//          8-way unrolled gathers, dinv merged into scan1.
// ---------------------------------------------------------------------------

#define MAXN 100000
#define MAXE 3200000
#define INC  512
#define HID  40
#define OUTC 20

__device__ int   g_deg[MAXN];
__device__ int   g_off[MAXN];
__device__ int   g_fill[MAXN];
__device__ int   g_bsum[256];
__device__ int   g_bpre[256];
__device__ int   g_csr[MAXE];
__device__ float g_dinv[MAXN];
__device__ float g_hs1[MAXN * HID];   // (x@W1)*dinv
__device__ float g_hs2[MAXN * OUTC];  // (z1@W2)*dinv

// ---- packed f32x2 helpers (Blackwell FFMA2) -------------------------------
#define FMA_F32X2(d, a, b, c) \
    asm("fma.rn.f32x2 %0, %1, %2, %3;" : "=l"(d) : "l"(a), "l"(b), "l"(c))
#define MUL_F32X2(d, a, b) \
    asm("mul.rn.f32x2 %0, %1, %2;" : "=l"(d) : "l"(a), "l"(b))
#define PACK_F32X2(d, f) \
    asm("mov.b64 %0, {%1, %1};" : "=l"(d) : "f"(f))

typedef unsigned long long u64;

// ---------------------------------------------------------------------------
__global__ void k_zero(int n) {
    int i = blockIdx.x * blockDim.x + threadIdx.x;
    if (i < n) { g_deg[i] = 0; g_fill[i] = 0; }
}

__global__ void k_hist(const int* __restrict__ dst, int E) {
    int e = blockIdx.x * blockDim.x + threadIdx.x;
    if (e < E) atomicAdd(&g_deg[dst[e]], 1);
}

// scan chunk of 512 + compute dinv from deg (merged former k_dinv)
__global__ void k_scan1(int n) {
    __shared__ int s[512];
    int t = threadIdx.x;
    int i = blockIdx.x * 512 + t;
    int v = (i < n) ? g_deg[i] : 0;
    if (i < n) g_dinv[i] = rsqrtf((float)(v + 1));   // +1 self-loop
    s[t] = v;
    __syncthreads();
    for (int d = 1; d < 512; d <<= 1) {
        int a = (t >= d) ? s[t - d] : 0;
        __syncthreads();
        s[t] += a;
        __syncthreads();
    }
    if (i < n) g_off[i] = s[t] - v;
    if (t == 511) g_bsum[blockIdx.x] = s[511];
}

__global__ void k_scan2(int nblk) {
    __shared__ int s[256];
    int t = threadIdx.x;
    int v = (t < nblk) ? g_bsum[t] : 0;
    s[t] = v;
    __syncthreads();
    for (int d = 1; d < 256; d <<= 1) {
        int a = (t >= d) ? s[t - d] : 0;
        __syncthreads();
        s[t] += a;
        __syncthreads();
    }
    if (t < nblk) g_bpre[t] = s[t] - v;
}

__global__ void k_scan3(int n) {
    int i = blockIdx.x * blockDim.x + threadIdx.x;
    if (i < n) g_off[i] += g_bpre[i >> 9];
}

__global__ void k_fill(const int* __restrict__ src, const int* __restrict__ dst, int E) {
    int e = blockIdx.x * blockDim.x + threadIdx.x;
    if (e < E) {
        int d = dst[e];
        int p = atomicAdd(&g_fill[d], 1);
        g_csr[g_off[d] + p] = src[e];
    }
}

// ---------------------------------------------------------------------------
// GEMM1: hs1[i][c] = dinv[i] * sum_k x[i][k] * W1[k][c]
// 256 nodes/block, 128 threads, 2 nodes/thread. K tiled by 32.
// Software prefetch: W row k+1 (10 x LDS.128) and x(k+1) loaded during the
// 40 FFMA2s of row k -> LDS latency (29cy) hidden by ~80cy of FMA issue.
// ---------------------------------------------------------------------------
__global__ void __launch_bounds__(128, 3) k_gemm1(const float* __restrict__ x,
                                                  const float* __restrict__ W1,
                                                  int n) {
    __shared__ float xt[256 * 33];                  // pad 33: conflict-free col reads
    __shared__ __align__(16) float Ws[33 * HID];    // row 32 = prefetch pad
    int t = threadIdx.x;
    int nbase = blockIdx.x * 256;
    u64 accA[HID / 2], accB[HID / 2];
#pragma unroll
    for (int j = 0; j < HID / 2; j++) { accA[j] = 0ULL; accB[j] = 0ULL; }

    for (int k0 = 0; k0 < INC; k0 += 32) {
        __syncthreads();
        // W chunk: 32 rows x 40 cols (contiguous); pad row 32 left stale (unused)
#pragma unroll
        for (int i = 0; i < 10; i++)
            Ws[t + i * 128] = W1[k0 * HID + t + i * 128];
        // x tile: 256 nodes x 32 k, float4 loads (16/thread, coalesced)
#pragma unroll
        for (int i = 0; i < 16; i++) {
            int idx = t + i * 128;
            int nn = idx >> 3;
            int kk = (idx & 7) << 2;
            int gnode = nbase + nn;
            float4 v = make_float4(0.f, 0.f, 0.f, 0.f);
            if (gnode < n) v = *(const float4*)&x[(size_t)gnode * INC + k0 + kk];
            xt[nn * 33 + kk + 0] = v.x;
            xt[nn * 33 + kk + 1] = v.y;
            xt[nn * 33 + kk + 2] = v.z;
            xt[nn * 33 + kk + 3] = v.w;
        }
        __syncthreads();

        const ulonglong2* Wv = (const ulonglong2*)Ws;
        // preload k = 0
        ulonglong2 w[10];
#pragma unroll
        for (int jj = 0; jj < 10; jj++) w[jj] = Wv[jj];
        float a0 = xt[t * 33];
        float a1 = xt[(t + 128) * 33];

#pragma unroll 4
        for (int k = 0; k < 32; k++) {
            u64 x0, x1;
            PACK_F32X2(x0, a0);
            PACK_F32X2(x1, a1);
            // prefetch next k (k=31 reads pad row/col: in-bounds, unused)
            float a0n = xt[t * 33 + k + 1];
            float a1n = xt[(t + 128) * 33 + k + 1];
            ulonglong2 wn[10];
#pragma unroll
            for (int jj = 0; jj < 10; jj++) wn[jj] = Wv[(k + 1) * 10 + jj];
            // 40 FFMA2 on current k
#pragma unroll
            for (int jj = 0; jj < 10; jj++) {
                FMA_F32X2(accA[2 * jj],     x0, w[jj].x, accA[2 * jj]);
                FMA_F32X2(accA[2 * jj + 1], x0, w[jj].y, accA[2 * jj + 1]);
                FMA_F32X2(accB[2 * jj],     x1, w[jj].x, accB[2 * jj]);
                FMA_F32X2(accB[2 * jj + 1], x1, w[jj].y, accB[2 * jj + 1]);
            }
            // rotate (renamed away by unroll)
#pragma unroll
            for (int jj = 0; jj < 10; jj++) w[jj] = wn[jj];
            a0 = a0n;
            a1 = a1n;
        }
    }
    int na = nbase + t;
    int nb = nbase + 128 + t;
    if (na < n) {
        float di = g_dinv[na];
        u64 dd; PACK_F32X2(dd, di);
        u64* op = (u64*)&g_hs1[(size_t)na * HID];
#pragma unroll
        for (int j = 0; j < HID / 2; j++) { u64 r; MUL_F32X2(r, accA[j], dd); op[j] = r; }
    }
    if (nb < n) {
        float di = g_dinv[nb];
        u64 dd; PACK_F32X2(dd, di);
        u64* op = (u64*)&g_hs1[(size_t)nb * HID];
#pragma unroll
        for (int j = 0; j < HID / 2; j++) { u64 r; MUL_F32X2(r, accB[j], dd); op[j] = r; }
    }
}

// ---------------------------------------------------------------------------
// Fused aggregation-1 + GEMM2: 10 threads/node gather z1 row (float4 each,
// 8-way unrolled), smem exchange, then 2 output channels/thread of
// hs2 = dinv * (z1 @ W2). No z1 global round-trip.
// ---------------------------------------------------------------------------
__global__ void __launch_bounds__(320) k_agg1g2(const float* __restrict__ b1,
                                                const float* __restrict__ W2,
                                                int n) {
    __shared__ float z1s[32 * HID];
    __shared__ float W2s[HID * OUTC];
    int t = threadIdx.x;
    for (int i = t; i < HID * OUTC; i += 320) W2s[i] = W2[i];

    int ln = t / 10;
    int lane10 = t % 10;
    int node = blockIdx.x * 32 + ln;
    int c4 = lane10 * 4;
    bool valid = (node < n);
    float di = 0.0f;

    if (valid) {
        const float* __restrict__ hs = g_hs1;
        float4 acc = __ldg((const float4*)&hs[(size_t)node * HID + c4]);  // self
        int o = g_off[node];
        int dcnt = g_deg[node];
        di = g_dinv[node];
        int j = 0;
        for (; j + 8 <= dcnt; j += 8) {
            int s0 = __ldg(&g_csr[o + j]);
            int s1 = __ldg(&g_csr[o + j + 1]);
            int s2 = __ldg(&g_csr[o + j + 2]);
            int s3 = __ldg(&g_csr[o + j + 3]);
            int s4 = __ldg(&g_csr[o + j + 4]);
            int s5 = __ldg(&g_csr[o + j + 5]);
            int s6 = __ldg(&g_csr[o + j + 6]);
            int s7 = __ldg(&g_csr[o + j + 7]);
            float4 v0 = __ldg((const float4*)&hs[(size_t)s0 * HID + c4]);
            float4 v1 = __ldg((const float4*)&hs[(size_t)s1 * HID + c4]);
            float4 v2 = __ldg((const float4*)&hs[(size_t)s2 * HID + c4]);
            float4 v3 = __ldg((const float4*)&hs[(size_t)s3 * HID + c4]);
            float4 v4 = __ldg((const float4*)&hs[(size_t)s4 * HID + c4]);
            float4 v5 = __ldg((const float4*)&hs[(size_t)s5 * HID + c4]);
            float4 v6 = __ldg((const float4*)&hs[(size_t)s6 * HID + c4]);
            float4 v7 = __ldg((const float4*)&hs[(size_t)s7 * HID + c4]);
            acc.x += (v0.x + v1.x) + (v2.x + v3.x) + ((v4.x + v5.x) + (v6.x + v7.x));
            acc.y += (v0.y + v1.y) + (v2.y + v3.y) + ((v4.y + v5.y) + (v6.y + v7.y));
            acc.z += (v0.z + v1.z) + (v2.z + v3.z) + ((v4.z + v5.z) + (v6.z + v7.z));
            acc.w += (v0.w + v1.w) + (v2.w + v3.w) + ((v4.w + v5.w) + (v6.w + v7.w));
        }
        for (; j < dcnt; j++) {
            int s0 = __ldg(&g_csr[o + j]);
            float4 v0 = __ldg((const float4*)&hs[(size_t)s0 * HID + c4]);
            acc.x += v0.x; acc.y += v0.y; acc.z += v0.z; acc.w += v0.w;
        }
        z1s[ln * HID + c4 + 0] = fmaxf(di * acc.x + __ldg(&b1[c4 + 0]), 0.0f);
        z1s[ln * HID + c4 + 1] = fmaxf(di * acc.y + __ldg(&b1[c4 + 1]), 0.0f);
        z1s[ln * HID + c4 + 2] = fmaxf(di * acc.z + __ldg(&b1[c4 + 2]), 0.0f);
        z1s[ln * HID + c4 + 3] = fmaxf(di * acc.w + __ldg(&b1[c4 + 3]), 0.0f);
    }
    __syncthreads();

    if (valid) {
        int c = lane10 * 2;
        float s0 = 0.0f, s1 = 0.0f;
#pragma unroll
        for (int k = 0; k < HID; k++) {
            float z = z1s[ln * HID + k];
            s0 = fmaf(z, W2s[k * OUTC + c],     s0);
            s1 = fmaf(z, W2s[k * OUTC + c + 1], s1);
        }
        g_hs2[(size_t)node * OUTC + c]     = di * s0;
        g_hs2[(size_t)node * OUTC + c + 1] = di * s1;
    }
}

// ---------------------------------------------------------------------------
// Aggregation layer 2: 5 threads/node, float4 each (20 ch), 8-way unroll.
// ---------------------------------------------------------------------------
__global__ void __launch_bounds__(320) k_agg2(const float* __restrict__ b2,
                                              float* __restrict__ out, int n) {
    int t = threadIdx.x;
    int node = blockIdx.x * 64 + t / 5;
    int c4 = (t % 5) * 4;
    if (node >= n) return;
    const float* __restrict__ hs = g_hs2;
    float4 acc = __ldg((const float4*)&hs[(size_t)node * OUTC + c4]);  // self
    int o = g_off[node];
    int dcnt = g_deg[node];
    int j = 0;
    for (; j + 8 <= dcnt; j += 8) {
        int s0 = __ldg(&g_csr[o + j]);
        int s1 = __ldg(&g_csr[o + j + 1]);
        int s2 = __ldg(&g_csr[o + j + 2]);
        int s3 = __ldg(&g_csr[o + j + 3]);
        int s4 = __ldg(&g_csr[o + j + 4]);
        int s5 = __ldg(&g_csr[o + j + 5]);
        int s6 = __ldg(&g_csr[o + j + 6]);
        int s7 = __ldg(&g_csr[o + j + 7]);
        float4 v0 = __ldg((const float4*)&hs[(size_t)s0 * OUTC + c4]);
        float4 v1 = __ldg((const float4*)&hs[(size_t)s1 * OUTC + c4]);
        float4 v2 = __ldg((const float4*)&hs[(size_t)s2 * OUTC + c4]);
        float4 v3 = __ldg((const float4*)&hs[(size_t)s3 * OUTC + c4]);
        float4 v4 = __ldg((const float4*)&hs[(size_t)s4 * OUTC + c4]);
        float4 v5 = __ldg((const float4*)&hs[(size_t)s5 * OUTC + c4]);
        float4 v6 = __ldg((const float4*)&hs[(size_t)s6 * OUTC + c4]);
        float4 v7 = __ldg((const float4*)&hs[(size_t)s7 * OUTC + c4]);
        acc.x += (v0.x + v1.x) + (v2.x + v3.x) + ((v4.x + v5.x) + (v6.x + v7.x));
        acc.y += (v0.y + v1.y) + (v2.y + v3.y) + ((v4.y + v5.y) + (v6.y + v7.y));
        acc.z += (v0.z + v1.z) + (v2.z + v3.z) + ((v4.z + v5.z) + (v6.z + v7.z));
        acc.w += (v0.w + v1.w) + (v2.w + v3.w) + ((v4.w + v5.w) + (v6.w + v7.w));
    }
    for (; j < dcnt; j++) {
        int s0 = __ldg(&g_csr[o + j]);
        float4 v0 = __ldg((const float4*)&hs[(size_t)s0 * OUTC + c4]);
        acc.x += v0.x; acc.y += v0.y; acc.z += v0.z; acc.w += v0.w;
    }
    float di = g_dinv[node];
    float4 r;
    r.x = di * acc.x + __ldg(&b2[c4 + 0]);
    r.y = di * acc.y + __ldg(&b2[c4 + 1]);
    r.z = di * acc.z + __ldg(&b2[c4 + 2]);
    r.w = di * acc.w + __ldg(&b2[c4 + 3]);
    *(float4*)&out[(size_t)node * OUTC + c4] = r;
}

// ---------------------------------------------------------------------------
extern "C" void kernel_launch(void* const* d_in, const int* in_sizes, int n_in,
                              void* d_out, int out_size) {
    const float* x  = (const float*)d_in[0];
    const int*   ei = (const int*)  d_in[1];
    const float* W1 = (const float*)d_in[2];
    const float* b1 = (const float*)d_in[3];
    const float* W2 = (const float*)d_in[4];
    const float* b2 = (const float*)d_in[5];
    float* out = (float*)d_out;

    int n = in_sizes[0] / INC;   // 100000
    int E = in_sizes[1] / 2;     // 3200000
    const int* src = ei;
    const int* dst = ei + E;

    int nb_n = (n + 255) / 256;
    int nb_e = (E + 255) / 256;
    int nblk = (n + 511) / 512;

    k_zero  <<<nb_n, 256>>>(n);                    // 0
    k_hist  <<<nb_e, 256>>>(dst, E);               // 1
    k_scan1 <<<nblk, 512>>>(n);                    // 2  (also computes dinv)
    k_gemm1 <<<(n + 255) / 256, 128>>>(x, W1, n);  // 3  — ncu window
    k_scan2 <<<1, 256>>>(nblk);                    // 4
    k_scan3 <<<nb_n, 256>>>(n);                    // 5
    k_fill  <<<nb_e, 256>>>(src, dst, E);          // 6
    k_agg1g2<<<(n + 31) / 32, 320>>>(b1, W2, n);   // 7
    k_agg2  <<<(n + 63) / 64, 320>>>(b2, out, n);  // 8
}

// round 13
// speedup vs baseline: 1.9033x; 1.0629x over previous
#include <cuda_runtime.h>
#include <cuda_bf16.h>
#include <cstdint>

// ---------------------------------------------------------------------------
// GCN 2-layer encoder:
//   z1 = relu( D^-1/2 (A+I) D^-1/2 (x @ W1) + b1 )
//   out =      D^-1/2 (A+I) D^-1/2 (z1 @ W2) + b2
// Norm folded: hs = (x@W)*dinv ; out[d] = dinv[d]*(sum_{s in N(d)} hs[s] + hs[d]) + b
// Per-launch CSR build, gather-only aggregation, gemm2 fused into agg1.
// Round 10: gemm1 retiled to 4 nodes x 20 channels per thread ->
//           75% FMA instruction mix (was 54%), no manual prefetch/rotates.
// ---------------------------------------------------------------------------

#define MAXN 100000
#define MAXE 3200000
#define INC  512
#define HID  40
#define OUTC 20

__device__ int   g_deg[MAXN];
__device__ int   g_off[MAXN];
__device__ int   g_fill[MAXN];
__device__ int   g_bsum[256];
__device__ int   g_bpre[256];
__device__ int   g_csr[MAXE];
__device__ float g_dinv[MAXN];
__device__ float g_hs1[MAXN * HID];   // (x@W1)*dinv
__device__ float g_hs2[MAXN * OUTC];  // (z1@W2)*dinv

// ---- packed f32x2 helpers (Blackwell FFMA2) -------------------------------
#define FMA_F32X2(d, a, b, c) \
    asm("fma.rn.f32x2 %0, %1, %2, %3;" : "=l"(d) : "l"(a), "l"(b), "l"(c))
#define MUL_F32X2(d, a, b) \
    asm("mul.rn.f32x2 %0, %1, %2;" : "=l"(d) : "l"(a), "l"(b))
#define PACK_F32X2(d, f) \
    asm("mov.b64 %0, {%1, %1};" : "=l"(d) : "f"(f))

typedef unsigned long long u64;

// ---------------------------------------------------------------------------
__global__ void k_zero(int n) {
    int i = blockIdx.x * blockDim.x + threadIdx.x;
    if (i < n) { g_deg[i] = 0; g_fill[i] = 0; }
}

__global__ void k_hist(const int* __restrict__ dst, int E) {
    int e = blockIdx.x * blockDim.x + threadIdx.x;
    if (e < E) atomicAdd(&g_deg[dst[e]], 1);
}

// scan chunk of 512 + compute dinv from deg
__global__ void k_scan1(int n) {
    __shared__ int s[512];
    int t = threadIdx.x;
    int i = blockIdx.x * 512 + t;
    int v = (i < n) ? g_deg[i] : 0;
    if (i < n) g_dinv[i] = rsqrtf((float)(v + 1));   // +1 self-loop
    s[t] = v;
    __syncthreads();
    for (int d = 1; d < 512; d <<= 1) {
        int a = (t >= d) ? s[t - d] : 0;
        __syncthreads();
        s[t] += a;
        __syncthreads();
    }
    if (i < n) g_off[i] = s[t] - v;
    if (t == 511) g_bsum[blockIdx.x] = s[511];
}

__global__ void k_scan2(int nblk) {
    __shared__ int s[256];
    int t = threadIdx.x;
    int v = (t < nblk) ? g_bsum[t] : 0;
    s[t] = v;
    __syncthreads();
    for (int d = 1; d < 256; d <<= 1) {
        int a = (t >= d) ? s[t - d] : 0;
        __syncthreads();
        s[t] += a;
        __syncthreads();
    }
    if (t < nblk) g_bpre[t] = s[t] - v;
}

__global__ void k_scan3(int n) {
    int i = blockIdx.x * blockDim.x + threadIdx.x;
    if (i < n) g_off[i] += g_bpre[i >> 9];
}

__global__ void k_fill(const int* __restrict__ src, const int* __restrict__ dst, int E) {
    int e = blockIdx.x * blockDim.x + threadIdx.x;
    if (e < E) {
        int d = dst[e];
        int p = atomicAdd(&g_fill[d], 1);
        g_csr[g_off[d] + p] = src[e];
    }
}

// ---------------------------------------------------------------------------
// GEMM1: hs1[i][c] = dinv[i] * sum_k x[i][k] * W1[k][c]
// 256 nodes/block, 128 threads. Thread tile: 4 nodes x 20 channels
//   (s = t>>1 -> nodes s*4..s*4+3,  h = t&1 -> channels h*20..h*20+19).
// Per k: 4 LDS.32 (x) + 5 LDS.128 (W) + 4 PACK + 40 FFMA2 -> ~75% FMA mix.
// ---------------------------------------------------------------------------
__global__ void __launch_bounds__(128, 3) k_gemm1(const float* __restrict__ x,
                                                  const float* __restrict__ W1,
                                                  int n) {
    __shared__ float xt[256 * 33];                 // pad 33: 2-way worst case
    __shared__ __align__(16) float Ws[32 * HID];   // 32 rows x 40 cols
    int t = threadIdx.x;
    int h = t & 1;          // channel half: cols [h*20, h*20+20)
    int s = t >> 1;         // node slot: nodes s*4 .. s*4+3
    int nbase = blockIdx.x * 256;

    u64 acc[4][10];         // [node][channel-pair]
#pragma unroll
    for (int i = 0; i < 4; i++)
#pragma unroll
        for (int j = 0; j < 10; j++) acc[i][j] = 0ULL;

    for (int k0 = 0; k0 < INC; k0 += 32) {
        __syncthreads();
        // W chunk: 32 rows x 40 cols, contiguous (1280 floats, 10/thread)
#pragma unroll
        for (int i = 0; i < 10; i++)
            Ws[t + i * 128] = W1[k0 * HID + t + i * 128];
        // x tile: 256 nodes x 32 k, float4 loads (16/thread, coalesced)
#pragma unroll
        for (int i = 0; i < 16; i++) {
            int idx = t + i * 128;
            int nn = idx >> 3;
            int kk = (idx & 7) << 2;
            int gnode = nbase + nn;
            float4 v = make_float4(0.f, 0.f, 0.f, 0.f);
            if (gnode < n) v = *(const float4*)&x[(size_t)gnode * INC + k0 + kk];
            xt[nn * 33 + kk + 0] = v.x;
            xt[nn * 33 + kk + 1] = v.y;
            xt[nn * 33 + kk + 2] = v.z;
            xt[nn * 33 + kk + 3] = v.w;
        }
        __syncthreads();

        const ulonglong2* Wv = (const ulonglong2*)Ws;   // 10 u2 per 40-col row
#pragma unroll 8
        for (int k = 0; k < 32; k++) {
            float a0 = xt[(s * 4 + 0) * 33 + k];
            float a1 = xt[(s * 4 + 1) * 33 + k];
            float a2 = xt[(s * 4 + 2) * 33 + k];
            float a3 = xt[(s * 4 + 3) * 33 + k];
            u64 x0, x1, x2, x3;
            PACK_F32X2(x0, a0);
            PACK_F32X2(x1, a1);
            PACK_F32X2(x2, a2);
            PACK_F32X2(x3, a3);
#pragma unroll
            for (int jj = 0; jj < 5; jj++) {
                ulonglong2 w = Wv[k * 10 + h * 5 + jj];   // 4 channels
                FMA_F32X2(acc[0][2 * jj],     x0, w.x, acc[0][2 * jj]);
                FMA_F32X2(acc[0][2 * jj + 1], x0, w.y, acc[0][2 * jj + 1]);
                FMA_F32X2(acc[1][2 * jj],     x1, w.x, acc[1][2 * jj]);
                FMA_F32X2(acc[1][2 * jj + 1], x1, w.y, acc[1][2 * jj + 1]);
                FMA_F32X2(acc[2][2 * jj],     x2, w.x, acc[2][2 * jj]);
                FMA_F32X2(acc[2][2 * jj + 1], x2, w.y, acc[2][2 * jj + 1]);
                FMA_F32X2(acc[3][2 * jj],     x3, w.x, acc[3][2 * jj]);
                FMA_F32X2(acc[3][2 * jj + 1], x3, w.y, acc[3][2 * jj + 1]);
            }
        }
    }

    // epilogue: node = nbase + s*4 + i, channels [h*20, h*20+20) = 5 STG.128
#pragma unroll
    for (int i = 0; i < 4; i++) {
        int node = nbase + s * 4 + i;
        if (node < n) {
            float di = g_dinv[node];
            u64 dd; PACK_F32X2(dd, di);
            ulonglong2* op = (ulonglong2*)&g_hs1[(size_t)node * HID + h * 20];
#pragma unroll
            for (int jj = 0; jj < 5; jj++) {
                ulonglong2 r;
                MUL_F32X2(r.x, acc[i][2 * jj],     dd);
                MUL_F32X2(r.y, acc[i][2 * jj + 1], dd);
                op[jj] = r;
            }
        }
    }
}

// ---------------------------------------------------------------------------
// Fused aggregation-1 + GEMM2: 10 threads/node gather z1 row (float4 each,
// 8-way unrolled), smem exchange, then 2 output channels/thread of
// hs2 = dinv * (z1 @ W2). No z1 global round-trip.
// ---------------------------------------------------------------------------
__global__ void __launch_bounds__(320) k_agg1g2(const float* __restrict__ b1,
                                                const float* __restrict__ W2,
                                                int n) {
    __shared__ float z1s[32 * HID];
    __shared__ float W2s[HID * OUTC];
    int t = threadIdx.x;
    for (int i = t; i < HID * OUTC; i += 320) W2s[i] = W2[i];

    int ln = t / 10;
    int lane10 = t % 10;
    int node = blockIdx.x * 32 + ln;
    int c4 = lane10 * 4;
    bool valid = (node < n);
    float di = 0.0f;

    if (valid) {
        const float* __restrict__ hs = g_hs1;
        float4 acc = __ldg((const float4*)&hs[(size_t)node * HID + c4]);  // self
        int o = g_off[node];
        int dcnt = g_deg[node];
        di = g_dinv[node];
        int j = 0;
        for (; j + 8 <= dcnt; j += 8) {
            int s0 = __ldg(&g_csr[o + j]);
            int s1 = __ldg(&g_csr[o + j + 1]);
            int s2 = __ldg(&g_csr[o + j + 2]);
            int s3 = __ldg(&g_csr[o + j + 3]);
            int s4 = __ldg(&g_csr[o + j + 4]);
            int s5 = __ldg(&g_csr[o + j + 5]);
            int s6 = __ldg(&g_csr[o + j + 6]);
            int s7 = __ldg(&g_csr[o + j + 7]);
            float4 v0 = __ldg((const float4*)&hs[(size_t)s0 * HID + c4]);
            float4 v1 = __ldg((const float4*)&hs[(size_t)s1 * HID + c4]);
            float4 v2 = __ldg((const float4*)&hs[(size_t)s2 * HID + c4]);
            float4 v3 = __ldg((const float4*)&hs[(size_t)s3 * HID + c4]);
            float4 v4 = __ldg((const float4*)&hs[(size_t)s4 * HID + c4]);
            float4 v5 = __ldg((const float4*)&hs[(size_t)s5 * HID + c4]);
            float4 v6 = __ldg((const float4*)&hs[(size_t)s6 * HID + c4]);
            float4 v7 = __ldg((const float4*)&hs[(size_t)s7 * HID + c4]);
            acc.x += (v0.x + v1.x) + (v2.x + v3.x) + ((v4.x + v5.x) + (v6.x + v7.x));
            acc.y += (v0.y + v1.y) + (v2.y + v3.y) + ((v4.y + v5.y) + (v6.y + v7.y));
            acc.z += (v0.z + v1.z) + (v2.z + v3.z) + ((v4.z + v5.z) + (v6.z + v7.z));
            acc.w += (v0.w + v1.w) + (v2.w + v3.w) + ((v4.w + v5.w) + (v6.w + v7.w));
        }
        for (; j < dcnt; j++) {
            int s0 = __ldg(&g_csr[o + j]);
            float4 v0 = __ldg((const float4*)&hs[(size_t)s0 * HID + c4]);
            acc.x += v0.x; acc.y += v0.y; acc.z += v0.z; acc.w += v0.w;
        }
        z1s[ln * HID + c4 + 0] = fmaxf(di * acc.x + __ldg(&b1[c4 + 0]), 0.0f);
        z1s[ln * HID + c4 + 1] = fmaxf(di * acc.y + __ldg(&b1[c4 + 1]), 0.0f);
        z1s[ln * HID + c4 + 2] = fmaxf(di * acc.z + __ldg(&b1[c4 + 2]), 0.0f);
        z1s[ln * HID + c4 + 3] = fmaxf(di * acc.w + __ldg(&b1[c4 + 3]), 0.0f);
    }
    __syncthreads();

    if (valid) {
        int c = lane10 * 2;
        float s0 = 0.0f, s1 = 0.0f;
#pragma unroll
        for (int k = 0; k < HID; k++) {
            float z = z1s[ln * HID + k];
            s0 = fmaf(z, W2s[k * OUTC + c],     s0);
            s1 = fmaf(z, W2s[k * OUTC + c + 1], s1);
        }
        g_hs2[(size_t)node * OUTC + c]     = di * s0;
        g_hs2[(size_t)node * OUTC + c + 1] = di * s1;
    }
}

// ---------------------------------------------------------------------------
// Aggregation layer 2: 5 threads/node, float4 each (20 ch), 8-way unroll.
// ---------------------------------------------------------------------------
__global__ void __launch_bounds__(320) k_agg2(const float* __restrict__ b2,
                                              float* __restrict__ out, int n) {
    int t = threadIdx.x;
    int node = blockIdx.x * 64 + t / 5;
    int c4 = (t % 5) * 4;
    if (node >= n) return;
    const float* __restrict__ hs = g_hs2;
    float4 acc = __ldg((const float4*)&hs[(size_t)node * OUTC + c4]);  // self
    int o = g_off[node];
    int dcnt = g_deg[node];
    int j = 0;
    for (; j + 8 <= dcnt; j += 8) {
        int s0 = __ldg(&g_csr[o + j]);
        int s1 = __ldg(&g_csr[o + j + 1]);
        int s2 = __ldg(&g_csr[o + j + 2]);
        int s3 = __ldg(&g_csr[o + j + 3]);
        int s4 = __ldg(&g_csr[o + j + 4]);
        int s5 = __ldg(&g_csr[o + j + 5]);
        int s6 = __ldg(&g_csr[o + j + 6]);
        int s7 = __ldg(&g_csr[o + j + 7]);
        float4 v0 = __ldg((const float4*)&hs[(size_t)s0 * OUTC + c4]);
        float4 v1 = __ldg((const float4*)&hs[(size_t)s1 * OUTC + c4]);
        float4 v2 = __ldg((const float4*)&hs[(size_t)s2 * OUTC + c4]);
        float4 v3 = __ldg((const float4*)&hs[(size_t)s3 * OUTC + c4]);
        float4 v4 = __ldg((const float4*)&hs[(size_t)s4 * OUTC + c4]);
        float4 v5 = __ldg((const float4*)&hs[(size_t)s5 * OUTC + c4]);
        float4 v6 = __ldg((const float4*)&hs[(size_t)s6 * OUTC + c4]);
        float4 v7 = __ldg((const float4*)&hs[(size_t)s7 * OUTC + c4]);
        acc.x += (v0.x + v1.x) + (v2.x + v3.x) + ((v4.x + v5.x) + (v6.x + v7.x));
        acc.y += (v0.y + v1.y) + (v2.y + v3.y) + ((v4.y + v5.y) + (v6.y + v7.y));
        acc.z += (v0.z + v1.z) + (v2.z + v3.z) + ((v4.z + v5.z) + (v6.z + v7.z));
        acc.w += (v0.w + v1.w) + (v2.w + v3.w) + ((v4.w + v5.w) + (v6.w + v7.w));
    }
    for (; j < dcnt; j++) {
        int s0 = __ldg(&g_csr[o + j]);
        float4 v0 = __ldg((const float4*)&hs[(size_t)s0 * OUTC + c4]);
        acc.x += v0.x; acc.y += v0.y; acc.z += v0.z; acc.w += v0.w;
    }
    float di = g_dinv[node];
    float4 r;
    r.x = di * acc.x + __ldg(&b2[c4 + 0]);
    r.y = di * acc.y + __ldg(&b2[c4 + 1]);
    r.z = di * acc.z + __ldg(&b2[c4 + 2]);
    r.w = di * acc.w + __ldg(&b2[c4 + 3]);
    *(float4*)&out[(size_t)node * OUTC + c4] = r;
}

// ---------------------------------------------------------------------------
extern "C" void kernel_launch(void* const* d_in, const int* in_sizes, int n_in,
                              void* d_out, int out_size) {
    const float* x  = (const float*)d_in[0];
    const int*   ei = (const int*)  d_in[1];
    const float* W1 = (const float*)d_in[2];
    const float* b1 = (const float*)d_in[3];
    const float* W2 = (const float*)d_in[4];
    const float* b2 = (const float*)d_in[5];
    float* out = (float*)d_out;

    int n = in_sizes[0] / INC;   // 100000
    int E = in_sizes[1] / 2;     // 3200000
    const int* src = ei;
    const int* dst = ei + E;

    int nb_n = (n + 255) / 256;
    int nb_e = (E + 255) / 256;
    int nblk = (n + 511) / 512;

    k_zero  <<<nb_n, 256>>>(n);                    // 0
    k_hist  <<<nb_e, 256>>>(dst, E);               // 1
    k_scan1 <<<nblk, 512>>>(n);                    // 2  (also computes dinv)
    k_gemm1 <<<(n + 255) / 256, 128>>>(x, W1, n);  // 3  — ncu window
    k_scan2 <<<1, 256>>>(nblk);                    // 4
    k_scan3 <<<nb_n, 256>>>(n);                    // 5
    k_fill  <<<nb_e, 256>>>(src, dst, E);          // 6
    k_agg1g2<<<(n + 31) / 32, 320>>>(b1, W2, n);   // 7
    k_agg2  <<<(n + 63) / 64, 320>>>(b2, out, n);  // 8
}

// round 14
// speedup vs baseline: 2.0104x; 1.0562x over previous
#include <cuda_runtime.h>
#include <cuda_bf16.h>
#include <cuda_fp16.h>
#include <cstdint>

// ---------------------------------------------------------------------------
// GCN 2-layer encoder. Norm folded: hs = (x@W)*dinv;
//   out[d] = dinv[d]*(sum_{s in N(d)} hs[s] + hs[d]) + b
// Round 13: gemm1 cp.async double-buffered pipeline (16-k stages);
//           hs1/hs2 gather tables stored fp16 (halve L2 gather bytes),
//           all accumulation fp32.
// ---------------------------------------------------------------------------

#define MAXN 100000
#define MAXE 3200000
#define INC  512
#define HID  40
#define OUTC 20

__device__ int     g_deg[MAXN];
__device__ int     g_off[MAXN];
__device__ int     g_fill[MAXN];
__device__ int     g_bsum[256];
__device__ int     g_bpre[256];
__device__ int     g_csr[MAXE];
__device__ float   g_dinv[MAXN];
__device__ __half2 g_hs1h[MAXN * (HID / 2)];   // (x@W1)*dinv, fp16
__device__ __half2 g_hs2h[MAXN * (OUTC / 2)];  // (z1@W2)*dinv, fp16

// ---- packed f32x2 helpers (Blackwell FFMA2) -------------------------------
#define FMA_F32X2(d, a, b, c) \
    asm("fma.rn.f32x2 %0, %1, %2, %3;" : "=l"(d) : "l"(a), "l"(b), "l"(c))
#define MUL_F32X2(d, a, b) \
    asm("mul.rn.f32x2 %0, %1, %2;" : "=l"(d) : "l"(a), "l"(b))
#define PACK_F32X2(d, f) \
    asm("mov.b64 %0, {%1, %1};" : "=l"(d) : "f"(f))
#define UNPACK_F32X2(lo, hi, in) \
    asm("mov.b64 {%0, %1}, %2;" : "=f"(lo), "=f"(hi) : "l"(in))

#define CP_COMMIT() asm volatile("cp.async.commit_group;" ::: "memory")
#define CP_WAIT1()  asm volatile("cp.async.wait_group 1;" ::: "memory")

typedef unsigned long long u64;

// ---------------------------------------------------------------------------
__global__ void k_zero(int n) {
    int i = blockIdx.x * blockDim.x + threadIdx.x;
    if (i < n) { g_deg[i] = 0; g_fill[i] = 0; }
}

__global__ void k_hist(const int* __restrict__ dst, int E) {
    int e = blockIdx.x * blockDim.x + threadIdx.x;
    if (e < E) atomicAdd(&g_deg[dst[e]], 1);
}

// scan chunk of 512 + compute dinv from deg
__global__ void k_scan1(int n) {
    __shared__ int s[512];
    int t = threadIdx.x;
    int i = blockIdx.x * 512 + t;
    int v = (i < n) ? g_deg[i] : 0;
    if (i < n) g_dinv[i] = rsqrtf((float)(v + 1));   // +1 self-loop
    s[t] = v;
    __syncthreads();
    for (int d = 1; d < 512; d <<= 1) {
        int a = (t >= d) ? s[t - d] : 0;
        __syncthreads();
        s[t] += a;
        __syncthreads();
    }
    if (i < n) g_off[i] = s[t] - v;
    if (t == 511) g_bsum[blockIdx.x] = s[511];
}

__global__ void k_scan2(int nblk) {
    __shared__ int s[256];
    int t = threadIdx.x;
    int v = (t < nblk) ? g_bsum[t] : 0;
    s[t] = v;
    __syncthreads();
    for (int d = 1; d < 256; d <<= 1) {
        int a = (t >= d) ? s[t - d] : 0;
        __syncthreads();
        s[t] += a;
        __syncthreads();
    }
    if (t < nblk) g_bpre[t] = s[t] - v;
}

__global__ void k_scan3(int n) {
    int i = blockIdx.x * blockDim.x + threadIdx.x;
    if (i < n) g_off[i] += g_bpre[i >> 9];
}

__global__ void k_fill(const int* __restrict__ src, const int* __restrict__ dst, int E) {
    int e = blockIdx.x * blockDim.x + threadIdx.x;
    if (e < E) {
        int d = dst[e];
        int p = atomicAdd(&g_fill[d], 1);
        g_csr[g_off[d] + p] = src[e];
    }
}

// ---------------------------------------------------------------------------
// GEMM1: hs1[i][c] = dinv[i] * sum_k x[i][k] * W1[k][c]  -> fp16 table
// 256 nodes/block, 128 threads. Thread tile: 4 nodes x 20 channels
//   (h = t&1 -> channels h*20..+19; s = t>>1 -> nodes {s, s+64, s+128, s+192}).
// cp.async double-buffered 16-k stages: stage s+1 DRAM traffic overlaps
// stage s compute. 46 KB static smem, 3 CTAs/SM.
// ---------------------------------------------------------------------------
__global__ void __launch_bounds__(128, 3) k_gemm1(const float* __restrict__ x,
                                                  const float* __restrict__ W1,
                                                  int n) {
    __shared__ float xt[2][256 * 20];               // 16 k + 4 pad (16B rows)
    __shared__ __align__(16) float Ws[2][16 * HID]; // 16 rows x 40 cols
    int t = threadIdx.x;
    int h = t & 1;
    int s = t >> 1;
    int nbase = blockIdx.x * 256;

    u64 acc[4][10];
#pragma unroll
    for (int i = 0; i < 4; i++)
#pragma unroll
        for (int j = 0; j < 10; j++) acc[i][j] = 0ULL;

#define LOAD_STAGE(stg, b) do {                                               \
        int k0_ = (stg) * 16;                                                 \
        _Pragma("unroll")                                                     \
        for (int i_ = 0; i_ < 5; i_++) {                                      \
            int wi_ = t + i_ * 128;                                           \
            uint32_t d_ = (uint32_t)__cvta_generic_to_shared(&Ws[b][wi_]);    \
            asm volatile("cp.async.ca.shared.global [%0], [%1], 4;"           \
                         :: "r"(d_), "l"(W1 + k0_ * HID + wi_));              \
        }                                                                     \
        _Pragma("unroll")                                                     \
        for (int i_ = 0; i_ < 8; i_++) {                                      \
            int idx_ = t + i_ * 128;                                          \
            int nn_ = idx_ >> 2;                                              \
            int kk_ = (idx_ & 3) << 2;                                        \
            int gn_ = nbase + nn_;                                            \
            uint32_t d_ = (uint32_t)__cvta_generic_to_shared(                 \
                              &xt[b][nn_ * 20 + kk_]);                        \
            const float* sp_ = (gn_ < n) ? x + (size_t)gn_ * INC + k0_ + kk_  \
                                         : x;                                 \
            int sz_ = (gn_ < n) ? 16 : 0;                                     \
            asm volatile("cp.async.cg.shared.global [%0], [%1], 16, %2;"      \
                         :: "r"(d_), "l"(sp_), "r"(sz_));                     \
        }                                                                     \
    } while (0)

    LOAD_STAGE(0, 0);
    CP_COMMIT();

    const int NSTAGE = INC / 16;   // 32
    for (int st = 0; st < NSTAGE; st++) {
        int b = st & 1;
        if (st + 1 < NSTAGE) LOAD_STAGE(st + 1, (st + 1) & 1);
        CP_COMMIT();
        CP_WAIT1();          // stage st resident (this thread's copies)
        __syncthreads();     // ... and everyone else's

#pragma unroll 4
        for (int k = 0; k < 16; k++) {
            float a0 = xt[b][(s + 0)   * 20 + k];
            float a1 = xt[b][(s + 64)  * 20 + k];
            float a2 = xt[b][(s + 128) * 20 + k];
            float a3 = xt[b][(s + 192) * 20 + k];
            u64 x0, x1, x2, x3;
            PACK_F32X2(x0, a0);
            PACK_F32X2(x1, a1);
            PACK_F32X2(x2, a2);
            PACK_F32X2(x3, a3);
            const ulonglong2* Wv = (const ulonglong2*)&Ws[b][k * HID + h * 20];
#pragma unroll
            for (int jj = 0; jj < 5; jj++) {
                ulonglong2 w = Wv[jj];
                FMA_F32X2(acc[0][2 * jj],     x0, w.x, acc[0][2 * jj]);
                FMA_F32X2(acc[0][2 * jj + 1], x0, w.y, acc[0][2 * jj + 1]);
                FMA_F32X2(acc[1][2 * jj],     x1, w.x, acc[1][2 * jj]);
                FMA_F32X2(acc[1][2 * jj + 1], x1, w.y, acc[1][2 * jj + 1]);
                FMA_F32X2(acc[2][2 * jj],     x2, w.x, acc[2][2 * jj]);
                FMA_F32X2(acc[2][2 * jj + 1], x2, w.y, acc[2][2 * jj + 1]);
                FMA_F32X2(acc[3][2 * jj],     x3, w.x, acc[3][2 * jj]);
                FMA_F32X2(acc[3][2 * jj + 1], x3, w.y, acc[3][2 * jj + 1]);
            }
        }
        __syncthreads();     // buffer b free for stage st+2's cp.async
    }
#undef LOAD_STAGE

    // epilogue: node = nbase + s + i*64, channels [h*20, +20) -> fp16
#pragma unroll
    for (int i = 0; i < 4; i++) {
        int node = nbase + s + i * 64;
        if (node < n) {
            float di = g_dinv[node];
            u64 dd; PACK_F32X2(dd, di);
            __half2* op = &g_hs1h[(size_t)node * (HID / 2) + h * 10];
#pragma unroll
            for (int jj = 0; jj < 10; jj++) {
                u64 r; MUL_F32X2(r, acc[i][jj], dd);
                float lo, hi; UNPACK_F32X2(lo, hi, r);
                op[jj] = __floats2half2_rn(lo, hi);
            }
        }
    }
}

// ---------------------------------------------------------------------------
// Fused aggregation-1 + GEMM2: 10 threads/node gather z1 row (uint2 = 4 fp16
// channels each, 8-way unrolled), fp32 accumulate, smem exchange, then
// 2 output channels/thread of hs2 = dinv * (z1 @ W2) -> fp16 table.
// ---------------------------------------------------------------------------
__global__ void __launch_bounds__(320) k_agg1g2(const float* __restrict__ b1,
                                                const float* __restrict__ W2,
                                                int n) {
    __shared__ float z1s[32 * HID];
    __shared__ float W2s[HID * OUTC];
    int t = threadIdx.x;
    for (int i = t; i < HID * OUTC; i += 320) W2s[i] = W2[i];

    int ln = t / 10;
    int lane10 = t % 10;
    int node = blockIdx.x * 32 + ln;
    int c4 = lane10 * 4;
    bool valid = (node < n);
    float di = 0.0f;

    if (valid) {
        const uint2* __restrict__ hp =
            (const uint2*)g_hs1h;   // one uint2 = 4 fp16 channels
        // row stride in uint2 units: HID/4 = 10; this thread's column: lane10
#define GATHER1(sidx, ax, ay, az, aw) do {                                   \
            uint2 raw = __ldg(&hp[(size_t)(sidx) * 10 + lane10]);            \
            float2 f0 = __half22float2(*(__half2*)&raw.x);                   \
            float2 f1 = __half22float2(*(__half2*)&raw.y);                   \
            ax += f0.x; ay += f0.y; az += f1.x; aw += f1.y;                  \
        } while (0)
        float ax = 0.f, ay = 0.f, az = 0.f, aw = 0.f;
        GATHER1(node, ax, ay, az, aw);   // self term
        int o = g_off[node];
        int dcnt = g_deg[node];
        di = g_dinv[node];
        int j = 0;
        for (; j + 8 <= dcnt; j += 8) {
            int s0 = __ldg(&g_csr[o + j]);
            int s1 = __ldg(&g_csr[o + j + 1]);
            int s2 = __ldg(&g_csr[o + j + 2]);
            int s3 = __ldg(&g_csr[o + j + 3]);
            int s4 = __ldg(&g_csr[o + j + 4]);
            int s5 = __ldg(&g_csr[o + j + 5]);
            int s6 = __ldg(&g_csr[o + j + 6]);
            int s7 = __ldg(&g_csr[o + j + 7]);
            GATHER1(s0, ax, ay, az, aw);
            GATHER1(s1, ax, ay, az, aw);
            GATHER1(s2, ax, ay, az, aw);
            GATHER1(s3, ax, ay, az, aw);
            GATHER1(s4, ax, ay, az, aw);
            GATHER1(s5, ax, ay, az, aw);
            GATHER1(s6, ax, ay, az, aw);
            GATHER1(s7, ax, ay, az, aw);
        }
        for (; j < dcnt; j++) {
            int s0 = __ldg(&g_csr[o + j]);
            GATHER1(s0, ax, ay, az, aw);
        }
#undef GATHER1
        z1s[ln * HID + c4 + 0] = fmaxf(di * ax + __ldg(&b1[c4 + 0]), 0.0f);
        z1s[ln * HID + c4 + 1] = fmaxf(di * ay + __ldg(&b1[c4 + 1]), 0.0f);
        z1s[ln * HID + c4 + 2] = fmaxf(di * az + __ldg(&b1[c4 + 2]), 0.0f);
        z1s[ln * HID + c4 + 3] = fmaxf(di * aw + __ldg(&b1[c4 + 3]), 0.0f);
    }
    __syncthreads();

    if (valid) {
        int c = lane10 * 2;
        float s0 = 0.0f, s1 = 0.0f;
#pragma unroll
        for (int k = 0; k < HID; k++) {
            float z = z1s[ln * HID + k];
            s0 = fmaf(z, W2s[k * OUTC + c],     s0);
            s1 = fmaf(z, W2s[k * OUTC + c + 1], s1);
        }
        g_hs2h[(size_t)node * (OUTC / 2) + lane10] =
            __floats2half2_rn(di * s0, di * s1);
    }
}

// ---------------------------------------------------------------------------
// Aggregation layer 2: 5 threads/node, uint2 (4 fp16 ch) each, 8-way unroll,
// fp32 accumulate + bias, fp32 output.
// ---------------------------------------------------------------------------
__global__ void __launch_bounds__(320) k_agg2(const float* __restrict__ b2,
                                              float* __restrict__ out, int n) {
    int t = threadIdx.x;
    int node = blockIdx.x * 64 + t / 5;
    int lane5 = t % 5;
    int c4 = lane5 * 4;
    if (node >= n) return;
    const uint2* __restrict__ hp = (const uint2*)g_hs2h;  // stride OUTC/4 = 5
#define GATHER2(sidx, ax, ay, az, aw) do {                                   \
        uint2 raw = __ldg(&hp[(size_t)(sidx) * 5 + lane5]);                  \
        float2 f0 = __half22float2(*(__half2*)&raw.x);                       \
        float2 f1 = __half22float2(*(__half2*)&raw.y);                       \
        ax += f0.x; ay += f0.y; az += f1.x; aw += f1.y;                      \
    } while (0)
    float ax = 0.f, ay = 0.f, az = 0.f, aw = 0.f;
    GATHER2(node, ax, ay, az, aw);   // self term
    int o = g_off[node];
    int dcnt = g_deg[node];
    int j = 0;
    for (; j + 8 <= dcnt; j += 8) {
        int s0 = __ldg(&g_csr[o + j]);
        int s1 = __ldg(&g_csr[o + j + 1]);
        int s2 = __ldg(&g_csr[o + j + 2]);
        int s3 = __ldg(&g_csr[o + j + 3]);
        int s4 = __ldg(&g_csr[o + j + 4]);
        int s5 = __ldg(&g_csr[o + j + 5]);
        int s6 = __ldg(&g_csr[o + j + 6]);
        int s7 = __ldg(&g_csr[o + j + 7]);
        GATHER2(s0, ax, ay, az, aw);
        GATHER2(s1, ax, ay, az, aw);
        GATHER2(s2, ax, ay, az, aw);
        GATHER2(s3, ax, ay, az, aw);
        GATHER2(s4, ax, ay, az, aw);
        GATHER2(s5, ax, ay, az, aw);
        GATHER2(s6, ax, ay, az, aw);
        GATHER2(s7, ax, ay, az, aw);
    }
    for (; j < dcnt; j++) {
        int s0 = __ldg(&g_csr[o + j]);
        GATHER2(s0, ax, ay, az, aw);
    }
#undef GATHER2
    float di = g_dinv[node];
    float4 r;
    r.x = di * ax + __ldg(&b2[c4 + 0]);
    r.y = di * ay + __ldg(&b2[c4 + 1]);
    r.z = di * az + __ldg(&b2[c4 + 2]);
    r.w = di * aw + __ldg(&b2[c4 + 3]);
    *(float4*)&out[(size_t)node * OUTC + c4] = r;
}

// ---------------------------------------------------------------------------
extern "C" void kernel_launch(void* const* d_in, const int* in_sizes, int n_in,
                              void* d_out, int out_size) {
    const float* x  = (const float*)d_in[0];
    const int*   ei = (const int*)  d_in[1];
    const float* W1 = (const float*)d_in[2];
    const float* b1 = (const float*)d_in[3];
    const float* W2 = (const float*)d_in[4];
    const float* b2 = (const float*)d_in[5];
    float* out = (float*)d_out;

    int n = in_sizes[0] / INC;   // 100000
    int E = in_sizes[1] / 2;     // 3200000
    const int* src = ei;
    const int* dst = ei + E;

    int nb_n = (n + 255) / 256;
    int nb_e = (E + 255) / 256;
    int nblk = (n + 511) / 512;

    k_zero  <<<nb_n, 256>>>(n);                    // 0
    k_hist  <<<nb_e, 256>>>(dst, E);               // 1
    k_scan1 <<<nblk, 512>>>(n);                    // 2  (also computes dinv)
    k_gemm1 <<<(n + 255) / 256, 128>>>(x, W1, n);  // 3  — ncu window
    k_scan2 <<<1, 256>>>(nblk);                    // 4
    k_scan3 <<<nb_n, 256>>>(n);                    // 5
    k_fill  <<<nb_e, 256>>>(src, dst, E);          // 6
    k_agg1g2<<<(n + 31) / 32, 320>>>(b1, W2, n);   // 7
    k_agg2  <<<(n + 63) / 64, 320>>>(b2, out, n);  // 8
}